// round 7
// baseline (speedup 1.0000x reference)
#include <cuda_runtime.h>
#include <math_constants.h>

#define NUM_HEADS 32
#define NUM_KV    8
#define HEAD_DIM  128
#define HIDDEN    4096
#define BSZ       32
#define MAX_SEQ   4096
#define GROUP     4
#define QKV_OUT   6144
#define CHUNK     128
#define NCHUNK    32
// attention scale * log2(e): softmax in exp2 domain
#define QSCALE    (0.08838834764831845f * 1.4426950408889634f)

// GEMM tiling: BM=512, BK=8, 256 threads, per-thread 8m x 8b
#define GBM 512
#define GBK 8
#define WST 516
#define XST 36
#define QKV_SPLIT 24
#define WO_SPLIT  36

// attention smem layout (floats)
#define KROWF 132                        // K tile row stride
#define SM_K   0                         // 128*132 = 16896 floats
#define SM_Q   (128*KROWF)               // 512
#define SM_P   (SM_Q + 512)              // 512
#define SM_PS  (SM_P + 512)              // 1024 (2 halves x 128 tok x 4 g)
#define SM_WR  (SM_PS + 1024)            // 32
#define SM_TOT (SM_WR + 32)              // 18976 floats = 75904 bytes

// ---------------- scratch (no allocs allowed) ----------------
__device__ float g_qkv [BSZ * QKV_OUT];
__device__ float g_attn[BSZ * NUM_HEADS * HEAD_DIM];
__device__ float g_part[QKV_SPLIT * BSZ * QKV_OUT];
__device__ float g_po  [BSZ * NUM_KV * GROUP * NCHUNK * HEAD_DIM];
__device__ float g_pml [BSZ * NUM_KV * GROUP * NCHUNK * 2];

// packed fp32x2 FMA (Blackwell)
__device__ __forceinline__ void fma2(unsigned long long& d,
                                     unsigned long long a,
                                     unsigned long long b) {
    asm("fma.rn.f32x2 %0, %1, %2, %0;" : "+l"(d) : "l"(a), "l"(b));
}
__device__ __forceinline__ unsigned long long dup2(float v) {
    unsigned long long r;
    asm("mov.b64 %0, {%1, %1};" : "=l"(r) : "f"(v));
    return r;
}
__device__ __forceinline__ void unpack2(unsigned long long v, float& lo, float& hi) {
    asm("mov.b64 {%0,%1}, %2;" : "=f"(lo), "=f"(hi) : "l"(v));
}

// ---------------------------------------------------------------
// Split-K GEMM writing per-split partials (R4-measured form, unchanged)
// ---------------------------------------------------------------
__global__ void __launch_bounds__(256, 2)
gemm8x8_kernel(const float* __restrict__ W, const float* __restrict__ x,
               float* __restrict__ part, int M, int K, int nsplit)
{
    __shared__ __align__(16) float Ws[2][GBK][WST];
    __shared__ __align__(16) float Xs[2][GBK][XST];

    const int m0    = blockIdx.x * GBM;
    const int tot   = K / GBK;
    const int tile0 = (blockIdx.y * tot) / nsplit;
    const int tile1 = ((blockIdx.y + 1) * tot) / nsplit;

    const int t   = threadIdx.x;
    const int ty  = t >> 2;
    const int tx  = t & 3;
    const int r0  = t >> 1;
    const int wkv = t & 1;
    const int xb  = t & 31;
    const int xkv = t >> 5;

    float4 wst[4];
    float4 xst;

    {
        const float* wp = W + (size_t)(m0 + r0) * K + (size_t)tile0 * GBK + wkv * 4;
        #pragma unroll
        for (int i = 0; i < 4; i++)
            wst[i] = *reinterpret_cast<const float4*>(wp + (size_t)i * 128 * K);
        if (t < 64)
            xst = *reinterpret_cast<const float4*>(x + (size_t)xb * K + (size_t)tile0 * GBK + xkv * 4);

        #pragma unroll
        for (int i = 0; i < 4; i++) {
            int r = r0 + i * 128;
            Ws[0][wkv*4+0][r] = wst[i].x;
            Ws[0][wkv*4+1][r] = wst[i].y;
            Ws[0][wkv*4+2][r] = wst[i].z;
            Ws[0][wkv*4+3][r] = wst[i].w;
        }
        if (t < 64) {
            Xs[0][xkv*4+0][xb] = xst.x;
            Xs[0][xkv*4+1][xb] = xst.y;
            Xs[0][xkv*4+2][xb] = xst.z;
            Xs[0][xkv*4+3][xb] = xst.w;
        }
    }
    __syncthreads();

    unsigned long long acc[4][8];
    #pragma unroll
    for (int i = 0; i < 4; i++)
        #pragma unroll
        for (int j = 0; j < 8; j++) acc[i][j] = 0ull;

    int p = 0;
    for (int tile = tile0; tile < tile1; tile++) {
        const bool has_next = (tile + 1 < tile1);
        if (has_next) {
            const float* wp = W + (size_t)(m0 + r0) * K + (size_t)(tile + 1) * GBK + wkv * 4;
            #pragma unroll
            for (int i = 0; i < 4; i++)
                wst[i] = *reinterpret_cast<const float4*>(wp + (size_t)i * 128 * K);
            if (t < 64)
                xst = *reinterpret_cast<const float4*>(x + (size_t)xb * K + (size_t)(tile + 1) * GBK + xkv * 4);
        }

        #pragma unroll
        for (int k = 0; k < GBK; k++) {
            ulonglong2 w01 = *reinterpret_cast<const ulonglong2*>(&Ws[p][k][ty * 8]);
            ulonglong2 w23 = *reinterpret_cast<const ulonglong2*>(&Ws[p][k][ty * 8 + 4]);
            float4 xa = *reinterpret_cast<const float4*>(&Xs[p][k][tx * 8]);
            float4 xc = *reinterpret_cast<const float4*>(&Xs[p][k][tx * 8 + 4]);
            unsigned long long xd;
            xd = dup2(xa.x);
            fma2(acc[0][0], w01.x, xd); fma2(acc[1][0], w01.y, xd);
            fma2(acc[2][0], w23.x, xd); fma2(acc[3][0], w23.y, xd);
            xd = dup2(xa.y);
            fma2(acc[0][1], w01.x, xd); fma2(acc[1][1], w01.y, xd);
            fma2(acc[2][1], w23.x, xd); fma2(acc[3][1], w23.y, xd);
            xd = dup2(xa.z);
            fma2(acc[0][2], w01.x, xd); fma2(acc[1][2], w01.y, xd);
            fma2(acc[2][2], w23.x, xd); fma2(acc[3][2], w23.y, xd);
            xd = dup2(xa.w);
            fma2(acc[0][3], w01.x, xd); fma2(acc[1][3], w01.y, xd);
            fma2(acc[2][3], w23.x, xd); fma2(acc[3][3], w23.y, xd);
            xd = dup2(xc.x);
            fma2(acc[0][4], w01.x, xd); fma2(acc[1][4], w01.y, xd);
            fma2(acc[2][4], w23.x, xd); fma2(acc[3][4], w23.y, xd);
            xd = dup2(xc.y);
            fma2(acc[0][5], w01.x, xd); fma2(acc[1][5], w01.y, xd);
            fma2(acc[2][5], w23.x, xd); fma2(acc[3][5], w23.y, xd);
            xd = dup2(xc.z);
            fma2(acc[0][6], w01.x, xd); fma2(acc[1][6], w01.y, xd);
            fma2(acc[2][6], w23.x, xd); fma2(acc[3][6], w23.y, xd);
            xd = dup2(xc.w);
            fma2(acc[0][7], w01.x, xd); fma2(acc[1][7], w01.y, xd);
            fma2(acc[2][7], w23.x, xd); fma2(acc[3][7], w23.y, xd);
        }

        if (has_next) {
            int pn = p ^ 1;
            #pragma unroll
            for (int i = 0; i < 4; i++) {
                int r = r0 + i * 128;
                Ws[pn][wkv*4+0][r] = wst[i].x;
                Ws[pn][wkv*4+1][r] = wst[i].y;
                Ws[pn][wkv*4+2][r] = wst[i].z;
                Ws[pn][wkv*4+3][r] = wst[i].w;
            }
            if (t < 64) {
                Xs[pn][xkv*4+0][xb] = xst.x;
                Xs[pn][xkv*4+1][xb] = xst.y;
                Xs[pn][xkv*4+2][xb] = xst.z;
                Xs[pn][xkv*4+3][xb] = xst.w;
            }
        }
        __syncthreads();
        p ^= 1;
    }

    float* pp = part + (size_t)blockIdx.y * BSZ * M;
    #pragma unroll
    for (int bj = 0; bj < 8; bj++) {
        int b = tx * 8 + bj;
        float* dst = pp + (size_t)b * M + m0 + ty * 8;
        ulonglong2 lo = make_ulonglong2(acc[0][bj], acc[1][bj]);
        ulonglong2 hi = make_ulonglong2(acc[2][bj], acc[3][bj]);
        *reinterpret_cast<ulonglong2*>(dst)     = lo;
        *reinterpret_cast<ulonglong2*>(dst + 4) = hi;
    }
}

// ---------------------------------------------------------------
// reduce partials (unchanged)
// ---------------------------------------------------------------
__global__ void __launch_bounds__(256)
reduce_part_kernel(const float4* __restrict__ part, const float4* __restrict__ bias,
                   float4* __restrict__ out, int M4, int nsplit)
{
    int idx = blockIdx.x * 256 + threadIdx.x;
    if (idx >= BSZ * M4) return;
    const size_t step = (size_t)BSZ * M4;
    float4 a0 = bias ? bias[idx % M4] : make_float4(0.f, 0.f, 0.f, 0.f);
    float4 a1 = make_float4(0.f, 0.f, 0.f, 0.f);
    float4 a2 = a1, a3 = a1;
    int s = 0;
    for (; s + 4 <= nsplit; s += 4) {
        float4 p0 = part[(size_t)(s+0) * step + idx];
        float4 p1 = part[(size_t)(s+1) * step + idx];
        float4 p2 = part[(size_t)(s+2) * step + idx];
        float4 p3 = part[(size_t)(s+3) * step + idx];
        a0.x += p0.x; a0.y += p0.y; a0.z += p0.z; a0.w += p0.w;
        a1.x += p1.x; a1.y += p1.y; a1.z += p1.z; a1.w += p1.w;
        a2.x += p2.x; a2.y += p2.y; a2.z += p2.z; a2.w += p2.w;
        a3.x += p3.x; a3.y += p3.y; a3.z += p3.z; a3.w += p3.w;
    }
    for (; s < nsplit; s++) {
        float4 pv = part[(size_t)s * step + idx];
        a0.x += pv.x; a0.y += pv.y; a0.z += pv.z; a0.w += pv.w;
    }
    a0.x += a1.x + a2.x + a3.x;
    a0.y += a1.y + a2.y + a3.y;
    a0.z += a1.z + a2.z + a3.z;
    a0.w += a1.w + a2.w + a3.w;
    out[idx] = a0;
}

// ---------------------------------------------------------------
// Flash-decode partial v2: two-phase, no warp shuffles in hot path.
// grid (NCHUNK, NUM_KV, BSZ), 256 threads, dyn smem 75904 B.
// ---------------------------------------------------------------
__global__ void __launch_bounds__(256, 2)
attn_partial_kernel(const float* __restrict__ kvc,
                    const int*   __restrict__ seq_lens,
                    const int*   __restrict__ slot_map)
{
    extern __shared__ __align__(16) float sh[];

    int b   = blockIdx.z;
    int kvh = blockIdx.y;
    int c   = blockIdx.x;

    int seq   = seq_lens[b];
    int start = c * CHUNK;
    if (start >= seq) return;
    int end   = min(seq, start + CHUNK);
    int nval  = end - start;
    int slot  = slot_map[b];

    int tid  = threadIdx.x;
    int lane = tid & 31;
    int wid  = tid >> 5;   // 0..7

    const float* knew = &g_qkv[b * QKV_OUT + NUM_HEADS * HEAD_DIM            + kvh * HEAD_DIM];
    const float* vnew = &g_qkv[b * QKV_OUT + (NUM_HEADS + NUM_KV) * HEAD_DIM + kvh * HEAD_DIM];
    const size_t VPLANE = (size_t)BSZ * MAX_SEQ * NUM_KV * HEAD_DIM;

    // ---- load q (scaled) into smem ----
    if (tid < 128) {
        float4 q4 = *reinterpret_cast<const float4*>(
            &g_qkv[b * QKV_OUT + kvh * GROUP * HEAD_DIM + tid * 4]);
        q4.x *= QSCALE; q4.y *= QSCALE; q4.z *= QSCALE; q4.w *= QSCALE;
        *reinterpret_cast<float4*>(&sh[SM_Q + tid * 4]) = q4;
    }

    // ---- stage K tile into smem: 16 iters x 8 rows, unrolled x4 for MLP ----
    {
        #pragma unroll
        for (int it = 0; it < 16; it += 4) {
            float4 r[4];
            #pragma unroll
            for (int j = 0; j < 4; j++) {
                int row = (it + j) * 8 + wid;
                int s   = start + row;
                const float* src = (s == slot) ? knew
                    : &kvc[(((size_t)b * MAX_SEQ + s) * NUM_KV + kvh) * HEAD_DIM];
                r[j] = *reinterpret_cast<const float4*>(&src[lane * 4]);
            }
            #pragma unroll
            for (int j = 0; j < 4; j++) {
                int row = (it + j) * 8 + wid;
                *reinterpret_cast<float4*>(&sh[SM_K + row * KROWF + lane * 4]) = r[j];
            }
        }
    }
    __syncthreads();

    // ---- stage A: scores. thread pair (j, j+128) splits the 128 dims ----
    {
        int half = tid >> 7;        // 0 or 1
        int j    = tid & 127;       // token index within chunk
        const float* krow = &sh[SM_K + j * KROWF + half * 64];
        const float* qh   = &sh[SM_Q + half * 64];

        unsigned long long acc[4] = {0ull, 0ull, 0ull, 0ull};
        #pragma unroll
        for (int i = 0; i < 16; i++) {
            ulonglong2 kp = *reinterpret_cast<const ulonglong2*>(&krow[i * 4]);
            #pragma unroll
            for (int g = 0; g < 4; g++) {
                ulonglong2 qp = *reinterpret_cast<const ulonglong2*>(&qh[g * 128 + i * 4]);
                fma2(acc[g], qp.x, kp.x);
                fma2(acc[g], qp.y, kp.y);
            }
        }
        #pragma unroll
        for (int g = 0; g < 4; g++) {
            float lo, hi; unpack2(acc[g], lo, hi);
            sh[SM_PS + (half * 128 + j) * 4 + g] = lo + hi;
        }
    }
    __syncthreads();

    // ---- softmax (block-wide, per group) ----
    float sc[4];
    if (tid < 128) {
        int j = tid;
        #pragma unroll
        for (int g = 0; g < 4; g++) {
            sc[g] = sh[SM_PS + j * 4 + g] + sh[SM_PS + (128 + j) * 4 + g];
            if (j >= nval) sc[g] = -CUDART_INF_F;
        }
        float mx[4];
        #pragma unroll
        for (int g = 0; g < 4; g++) {
            mx[g] = sc[g];
            #pragma unroll
            for (int off = 16; off >= 1; off >>= 1)
                mx[g] = fmaxf(mx[g], __shfl_xor_sync(0xffffffffu, mx[g], off));
        }
        if (lane == 0) {
            #pragma unroll
            for (int g = 0; g < 4; g++) sh[SM_WR + wid * 4 + g] = mx[g];
        }
    }
    __syncthreads();

    float M[4];
    #pragma unroll
    for (int g = 0; g < 4; g++)
        M[g] = fmaxf(fmaxf(sh[SM_WR + 0*4 + g], sh[SM_WR + 1*4 + g]),
                     fmaxf(sh[SM_WR + 2*4 + g], sh[SM_WR + 3*4 + g]));
    __syncthreads();   // everyone has read WR; safe to overwrite with sums

    if (tid < 128) {
        float p[4], ls[4];
        #pragma unroll
        for (int g = 0; g < 4; g++) p[g] = exp2f(sc[g] - M[g]);
        *reinterpret_cast<float4*>(&sh[SM_P + tid * 4]) =
            make_float4(p[0], p[1], p[2], p[3]);
        #pragma unroll
        for (int g = 0; g < 4; g++) {
            ls[g] = p[g];
            #pragma unroll
            for (int off = 16; off >= 1; off >>= 1)
                ls[g] += __shfl_xor_sync(0xffffffffu, ls[g], off);
        }
        if (lane == 0) {
            #pragma unroll
            for (int g = 0; g < 4; g++) sh[SM_WR + wid * 4 + g] = ls[g];
        }
    }
    __syncthreads();

    // ---- stage B: V accumulation. warp w -> tokens w*16 .. w*16+15 ----
    unsigned long long oacc[4][2];
    #pragma unroll
    for (int g = 0; g < 4; g++) { oacc[g][0] = 0ull; oacc[g][1] = 0ull; }

    {
        int t0   = wid * 16;
        int tEnd = nval - t0;              // valid tokens for this warp
        if (tEnd > 16) tEnd = 16;

        auto ldv = [&](int t) -> float4 {
            if (t >= tEnd) return make_float4(0.f, 0.f, 0.f, 0.f);
            int s = start + t0 + t;
            const float* src = (s == slot) ? vnew
                : &kvc[VPLANE + (((size_t)b * MAX_SEQ + s) * NUM_KV + kvh) * HEAD_DIM];
            return *reinterpret_cast<const float4*>(&src[lane * 4]);
        };

        if (tEnd > 0) {
            float4 va = ldv(0), vb = ldv(1);
            for (int tt = 0; ; tt += 2) {
                bool more = (tt + 2 < tEnd);
                float4 na, nb;
                if (more) { na = ldv(tt + 2); nb = ldv(tt + 3); }

                float4 p4a = *reinterpret_cast<const float4*>(&sh[SM_P + (t0 + tt) * 4]);
                float4 p4b = (tt + 1 < 16)
                    ? *reinterpret_cast<const float4*>(&sh[SM_P + (t0 + tt + 1) * 4])
                    : make_float4(0.f, 0.f, 0.f, 0.f);

                ulonglong2 vap = *reinterpret_cast<const ulonglong2*>(&va);
                ulonglong2 vbp = *reinterpret_cast<const ulonglong2*>(&vb);
                unsigned long long pd;
                pd = dup2(p4a.x); fma2(oacc[0][0], vap.x, pd); fma2(oacc[0][1], vap.y, pd);
                pd = dup2(p4a.y); fma2(oacc[1][0], vap.x, pd); fma2(oacc[1][1], vap.y, pd);
                pd = dup2(p4a.z); fma2(oacc[2][0], vap.x, pd); fma2(oacc[2][1], vap.y, pd);
                pd = dup2(p4a.w); fma2(oacc[3][0], vap.x, pd); fma2(oacc[3][1], vap.y, pd);
                pd = dup2(p4b.x); fma2(oacc[0][0], vbp.x, pd); fma2(oacc[0][1], vbp.y, pd);
                pd = dup2(p4b.y); fma2(oacc[1][0], vbp.x, pd); fma2(oacc[1][1], vbp.y, pd);
                pd = dup2(p4b.z); fma2(oacc[2][0], vbp.x, pd); fma2(oacc[2][1], vbp.y, pd);
                pd = dup2(p4b.w); fma2(oacc[3][0], vbp.x, pd); fma2(oacc[3][1], vbp.y, pd);

                if (!more) break;
                va = na; vb = nb;
            }
        }
    }
    __syncthreads();   // K tile no longer needed; reuse as o merge buffer

    // ---- merge: o_s[w][g][128] in the K-tile region ----
    {
        float* o_s = &sh[SM_K];
        #pragma unroll
        for (int g = 0; g < 4; g++) {
            float l0, h0, l1, h1;
            unpack2(oacc[g][0], l0, h0);
            unpack2(oacc[g][1], l1, h1);
            *reinterpret_cast<float4*>(&o_s[(wid * 4 + g) * 128 + lane * 4]) =
                make_float4(l0, h0, l1, h1);
        }
    }
    __syncthreads();

    {
        const float* o_s = &sh[SM_K];
        int d  = tid & 127;
        #pragma unroll
        for (int g2 = 0; g2 < 2; g2++) {
            int g = (tid >> 7) + g2 * 2;
            float sum = 0.f;
            #pragma unroll
            for (int w = 0; w < 8; w++)
                sum += o_s[(w * 4 + g) * 128 + d];
            size_t pidx = (((size_t)b * NUM_KV + kvh) * GROUP + g) * NCHUNK + c;
            g_po[pidx * HEAD_DIM + d] = sum;
        }
        if (tid < 4) {
            int g = tid;
            float L = sh[SM_WR + 0*4 + g] + sh[SM_WR + 1*4 + g]
                    + sh[SM_WR + 2*4 + g] + sh[SM_WR + 3*4 + g];
            size_t pidx = (((size_t)b * NUM_KV + kvh) * GROUP + g) * NCHUNK + c;
            g_pml[pidx * 2]     = M[g];
            g_pml[pidx * 2 + 1] = L;
        }
    }
}

// ---------------------------------------------------------------
// Chunk merge (unchanged)
// ---------------------------------------------------------------
__global__ void __launch_bounds__(128)
attn_reduce_kernel(const int* __restrict__ seq_lens)
{
    int h = blockIdx.x;
    int b = blockIdx.y;
    int d = threadIdx.x;
    int lane = d & 31, warp = d >> 5;
    int seq = seq_lens[b];
    int nch = (seq + CHUNK - 1) / CHUNK;
    int kvh = h >> 2, g = h & 3;

    size_t base = (((size_t)b * NUM_KV + kvh) * GROUP + g) * NCHUNK;

    __shared__ float es[NCHUNK];
    __shared__ float Ls;

    if (warp == 0) {
        float mm = -CUDART_INF_F, ll = 0.f;
        if (lane < nch) {
            float2 ml = *reinterpret_cast<const float2*>(&g_pml[(base + lane) * 2]);
            mm = ml.x; ll = ml.y;
        }
        float M = mm;
        #pragma unroll
        for (int off = 16; off >= 1; off >>= 1)
            M = fmaxf(M, __shfl_xor_sync(0xffffffffu, M, off));
        float e = (lane < nch) ? exp2f(mm - M) : 0.f;
        float le = ll * e;
        #pragma unroll
        for (int off = 16; off >= 1; off >>= 1)
            le += __shfl_xor_sync(0xffffffffu, le, off);
        es[lane] = e;
        if (lane == 0) Ls = le;
    }
    __syncthreads();

    float O0 = 0.f, O1 = 0.f, O2 = 0.f, O3 = 0.f;
    int cc = 0;
    for (; cc + 4 <= nch; cc += 4) {
        O0 += g_po[(base + cc + 0) * HEAD_DIM + d] * es[cc + 0];
        O1 += g_po[(base + cc + 1) * HEAD_DIM + d] * es[cc + 1];
        O2 += g_po[(base + cc + 2) * HEAD_DIM + d] * es[cc + 2];
        O3 += g_po[(base + cc + 3) * HEAD_DIM + d] * es[cc + 3];
    }
    for (; cc < nch; cc++)
        O0 += g_po[(base + cc) * HEAD_DIM + d] * es[cc];

    g_attn[(size_t)b * HIDDEN + h * HEAD_DIM + d] = ((O0 + O1) + (O2 + O3)) / Ls;
}

// ---------------------------------------------------------------
extern "C" void kernel_launch(void* const* d_in, const int* in_sizes, int n_in,
                              void* d_out, int out_size)
{
    const float* hidden = (const float*)d_in[0];
    const float* kvc    = (const float*)d_in[2];
    const int*   slot   = (const int*)  d_in[3];
    const int*   seql   = (const int*)  d_in[4];
    const float* Wqkv   = (const float*)d_in[5];
    const float* bqkv   = (const float*)d_in[6];
    const float* Wo     = (const float*)d_in[7];
    float*       out    = (float*)d_out;

    void *pq = nullptr, *pa = nullptr, *pp = nullptr;
    cudaGetSymbolAddress(&pq, g_qkv);
    cudaGetSymbolAddress(&pa, g_attn);
    cudaGetSymbolAddress(&pp, g_part);
    float* qkv  = (float*)pq;
    float* attn = (float*)pa;
    float* part = (float*)pp;

    const int ATT_SMEM = SM_TOT * 4;    // 75904 bytes
    cudaFuncSetAttribute(attn_partial_kernel,
                         cudaFuncAttributeMaxDynamicSharedMemorySize, ATT_SMEM);

    // 1) QKV projection: partials + reduce (bias folded into reduce)
    gemm8x8_kernel<<<dim3(QKV_OUT / GBM, QKV_SPLIT), 256>>>(Wqkv, hidden, part, QKV_OUT, HIDDEN, QKV_SPLIT);
    reduce_part_kernel<<<(BSZ * QKV_OUT / 4 + 255) / 256, 256>>>(
        (const float4*)part, (const float4*)bqkv, (float4*)qkv, QKV_OUT / 4, QKV_SPLIT);

    // 2) flash-decode partials (two-phase, shuffle-free hot path)
    attn_partial_kernel<<<dim3(NCHUNK, NUM_KV, BSZ), 256, ATT_SMEM>>>(kvc, seql, slot);

    // 3) merge partials
    attn_reduce_kernel<<<dim3(NUM_HEADS, BSZ), 128>>>(seql);

    // 4) output projection: partials + reduce (writes d_out directly)
    gemm8x8_kernel<<<dim3(HIDDEN / GBM, WO_SPLIT), 256>>>(Wo, attn, part, HIDDEN, HIDDEN, WO_SPLIT);
    reduce_part_kernel<<<(BSZ * HIDDEN / 4 + 255) / 256, 256>>>(
        (const float4*)part, nullptr, (float4*)out, HIDDEN / 4, WO_SPLIT);
}

// round 8
// speedup vs baseline: 1.2064x; 1.2064x over previous
#include <cuda_runtime.h>
#include <math_constants.h>

#define NUM_HEADS 32
#define NUM_KV    8
#define HEAD_DIM  128
#define HIDDEN    4096
#define BSZ       32
#define MAX_SEQ   4096
#define GROUP     4
#define QKV_OUT   6144
#define CHUNK     128
#define NCHUNK    32
// attention scale * log2(e): softmax in exp2 domain
#define QSCALE    (0.08838834764831845f * 1.4426950408889634f)

// GEMM tiling: BM=512, BK=8, 256 threads, per-thread 8m x 8b
#define GBM 512
#define GBK 8
#define WST 516
#define XST 36
#define QKV_SPLIT 24
#define WO_SPLIT  36

// ---------------- scratch (no allocs allowed) ----------------
__device__ float g_qkv [BSZ * QKV_OUT];
__device__ float g_attn[BSZ * NUM_HEADS * HEAD_DIM];
__device__ float g_part[QKV_SPLIT * BSZ * QKV_OUT];
__device__ float g_po  [BSZ * NUM_KV * GROUP * NCHUNK * HEAD_DIM];
__device__ float g_pml [BSZ * NUM_KV * GROUP * NCHUNK * 2];

// packed fp32x2 ops (Blackwell)
__device__ __forceinline__ void fma2(unsigned long long& d,
                                     unsigned long long a,
                                     unsigned long long b) {
    asm("fma.rn.f32x2 %0, %1, %2, %0;" : "+l"(d) : "l"(a), "l"(b));
}
__device__ __forceinline__ void mul2(unsigned long long& d, unsigned long long a) {
    asm("mul.rn.f32x2 %0, %0, %1;" : "+l"(d) : "l"(a));
}
__device__ __forceinline__ unsigned long long dup2(float v) {
    unsigned long long r;
    asm("mov.b64 %0, {%1, %1};" : "=l"(r) : "f"(v));
    return r;
}
__device__ __forceinline__ void unpack2(unsigned long long v, float& lo, float& hi) {
    asm("mov.b64 {%0,%1}, %2;" : "=f"(lo), "=f"(hi) : "l"(v));
}
__device__ __forceinline__ void lds128(float4& v, unsigned addr) {
    asm volatile("ld.shared.v4.f32 {%0,%1,%2,%3}, [%4];"
                 : "=f"(v.x), "=f"(v.y), "=f"(v.z), "=f"(v.w) : "r"(addr));
}

// ---------------------------------------------------------------
// Split-K GEMM writing per-split partials (R4-measured form, unchanged)
// ---------------------------------------------------------------
__global__ void __launch_bounds__(256, 2)
gemm8x8_kernel(const float* __restrict__ W, const float* __restrict__ x,
               float* __restrict__ part, int M, int K, int nsplit)
{
    __shared__ __align__(16) float Ws[2][GBK][WST];
    __shared__ __align__(16) float Xs[2][GBK][XST];

    const int m0    = blockIdx.x * GBM;
    const int tot   = K / GBK;
    const int tile0 = (blockIdx.y * tot) / nsplit;
    const int tile1 = ((blockIdx.y + 1) * tot) / nsplit;

    const int t   = threadIdx.x;
    const int ty  = t >> 2;
    const int tx  = t & 3;
    const int r0  = t >> 1;
    const int wkv = t & 1;
    const int xb  = t & 31;
    const int xkv = t >> 5;

    float4 wst[4];
    float4 xst;

    {
        const float* wp = W + (size_t)(m0 + r0) * K + (size_t)tile0 * GBK + wkv * 4;
        #pragma unroll
        for (int i = 0; i < 4; i++)
            wst[i] = *reinterpret_cast<const float4*>(wp + (size_t)i * 128 * K);
        if (t < 64)
            xst = *reinterpret_cast<const float4*>(x + (size_t)xb * K + (size_t)tile0 * GBK + xkv * 4);

        #pragma unroll
        for (int i = 0; i < 4; i++) {
            int r = r0 + i * 128;
            Ws[0][wkv*4+0][r] = wst[i].x;
            Ws[0][wkv*4+1][r] = wst[i].y;
            Ws[0][wkv*4+2][r] = wst[i].z;
            Ws[0][wkv*4+3][r] = wst[i].w;
        }
        if (t < 64) {
            Xs[0][xkv*4+0][xb] = xst.x;
            Xs[0][xkv*4+1][xb] = xst.y;
            Xs[0][xkv*4+2][xb] = xst.z;
            Xs[0][xkv*4+3][xb] = xst.w;
        }
    }
    __syncthreads();

    unsigned long long acc[4][8];
    #pragma unroll
    for (int i = 0; i < 4; i++)
        #pragma unroll
        for (int j = 0; j < 8; j++) acc[i][j] = 0ull;

    int p = 0;
    for (int tile = tile0; tile < tile1; tile++) {
        const bool has_next = (tile + 1 < tile1);
        if (has_next) {
            const float* wp = W + (size_t)(m0 + r0) * K + (size_t)(tile + 1) * GBK + wkv * 4;
            #pragma unroll
            for (int i = 0; i < 4; i++)
                wst[i] = *reinterpret_cast<const float4*>(wp + (size_t)i * 128 * K);
            if (t < 64)
                xst = *reinterpret_cast<const float4*>(x + (size_t)xb * K + (size_t)(tile + 1) * GBK + xkv * 4);
        }

        #pragma unroll
        for (int k = 0; k < GBK; k++) {
            ulonglong2 w01 = *reinterpret_cast<const ulonglong2*>(&Ws[p][k][ty * 8]);
            ulonglong2 w23 = *reinterpret_cast<const ulonglong2*>(&Ws[p][k][ty * 8 + 4]);
            float4 xa = *reinterpret_cast<const float4*>(&Xs[p][k][tx * 8]);
            float4 xc = *reinterpret_cast<const float4*>(&Xs[p][k][tx * 8 + 4]);
            unsigned long long xd;
            xd = dup2(xa.x);
            fma2(acc[0][0], w01.x, xd); fma2(acc[1][0], w01.y, xd);
            fma2(acc[2][0], w23.x, xd); fma2(acc[3][0], w23.y, xd);
            xd = dup2(xa.y);
            fma2(acc[0][1], w01.x, xd); fma2(acc[1][1], w01.y, xd);
            fma2(acc[2][1], w23.x, xd); fma2(acc[3][1], w23.y, xd);
            xd = dup2(xa.z);
            fma2(acc[0][2], w01.x, xd); fma2(acc[1][2], w01.y, xd);
            fma2(acc[2][2], w23.x, xd); fma2(acc[3][2], w23.y, xd);
            xd = dup2(xa.w);
            fma2(acc[0][3], w01.x, xd); fma2(acc[1][3], w01.y, xd);
            fma2(acc[2][3], w23.x, xd); fma2(acc[3][3], w23.y, xd);
            xd = dup2(xc.x);
            fma2(acc[0][4], w01.x, xd); fma2(acc[1][4], w01.y, xd);
            fma2(acc[2][4], w23.x, xd); fma2(acc[3][4], w23.y, xd);
            xd = dup2(xc.y);
            fma2(acc[0][5], w01.x, xd); fma2(acc[1][5], w01.y, xd);
            fma2(acc[2][5], w23.x, xd); fma2(acc[3][5], w23.y, xd);
            xd = dup2(xc.z);
            fma2(acc[0][6], w01.x, xd); fma2(acc[1][6], w01.y, xd);
            fma2(acc[2][6], w23.x, xd); fma2(acc[3][6], w23.y, xd);
            xd = dup2(xc.w);
            fma2(acc[0][7], w01.x, xd); fma2(acc[1][7], w01.y, xd);
            fma2(acc[2][7], w23.x, xd); fma2(acc[3][7], w23.y, xd);
        }

        if (has_next) {
            int pn = p ^ 1;
            #pragma unroll
            for (int i = 0; i < 4; i++) {
                int r = r0 + i * 128;
                Ws[pn][wkv*4+0][r] = wst[i].x;
                Ws[pn][wkv*4+1][r] = wst[i].y;
                Ws[pn][wkv*4+2][r] = wst[i].z;
                Ws[pn][wkv*4+3][r] = wst[i].w;
            }
            if (t < 64) {
                Xs[pn][xkv*4+0][xb] = xst.x;
                Xs[pn][xkv*4+1][xb] = xst.y;
                Xs[pn][xkv*4+2][xb] = xst.z;
                Xs[pn][xkv*4+3][xb] = xst.w;
            }
        }
        __syncthreads();
        p ^= 1;
    }

    float* pp = part + (size_t)blockIdx.y * BSZ * M;
    #pragma unroll
    for (int bj = 0; bj < 8; bj++) {
        int b = tx * 8 + bj;
        float* dst = pp + (size_t)b * M + m0 + ty * 8;
        ulonglong2 lo = make_ulonglong2(acc[0][bj], acc[1][bj]);
        ulonglong2 hi = make_ulonglong2(acc[2][bj], acc[3][bj]);
        *reinterpret_cast<ulonglong2*>(dst)     = lo;
        *reinterpret_cast<ulonglong2*>(dst + 4) = hi;
    }
}

// ---------------------------------------------------------------
// reduce partials (unchanged)
// ---------------------------------------------------------------
__global__ void __launch_bounds__(256)
reduce_part_kernel(const float4* __restrict__ part, const float4* __restrict__ bias,
                   float4* __restrict__ out, int M4, int nsplit)
{
    int idx = blockIdx.x * 256 + threadIdx.x;
    if (idx >= BSZ * M4) return;
    const size_t step = (size_t)BSZ * M4;
    float4 a0 = bias ? bias[idx % M4] : make_float4(0.f, 0.f, 0.f, 0.f);
    float4 a1 = make_float4(0.f, 0.f, 0.f, 0.f);
    float4 a2 = a1, a3 = a1;
    int s = 0;
    for (; s + 4 <= nsplit; s += 4) {
        float4 p0 = part[(size_t)(s+0) * step + idx];
        float4 p1 = part[(size_t)(s+1) * step + idx];
        float4 p2 = part[(size_t)(s+2) * step + idx];
        float4 p3 = part[(size_t)(s+3) * step + idx];
        a0.x += p0.x; a0.y += p0.y; a0.z += p0.z; a0.w += p0.w;
        a1.x += p1.x; a1.y += p1.y; a1.z += p1.z; a1.w += p1.w;
        a2.x += p2.x; a2.y += p2.y; a2.z += p2.z; a2.w += p2.w;
        a3.x += p3.x; a3.y += p3.y; a3.z += p3.z; a3.w += p3.w;
    }
    for (; s < nsplit; s++) {
        float4 pv = part[(size_t)s * step + idx];
        a0.x += pv.x; a0.y += pv.y; a0.z += pv.z; a0.w += pv.w;
    }
    a0.x += a1.x + a2.x + a3.x;
    a0.y += a1.y + a2.y + a3.y;
    a0.z += a1.z + a2.z + a3.z;
    a0.w += a1.w + a2.w + a3.w;
    out[idx] = a0;
}

// ---------------------------------------------------------------
// Flash-decode partial v3: online loop, subgroup-of-8 score reduce.
// grid (NCHUNK, NUM_KV, BSZ), 128 threads (4 warps).
// Warp iteration = 4 tokens (one per 8-lane subgroup for K/scores;
// all lanes share V accumulation with lane-owns-4-dims).
// ---------------------------------------------------------------
__global__ void __launch_bounds__(128, 4)
attn_partial_kernel(const float* __restrict__ kvc,
                    const int*   __restrict__ seq_lens,
                    const int*   __restrict__ slot_map)
{
    __shared__ __align__(16) float sm_q[512];          // 4 groups x 128 dims, scaled
    __shared__ __align__(16) float sm_o[4][4][128];    // [warp][g][dim]
    __shared__ float sm_m[4][4], sm_l[4][4], sm_e[4][4];

    int b   = blockIdx.z;
    int kvh = blockIdx.y;
    int c   = blockIdx.x;

    int seq   = seq_lens[b];
    int start = c * CHUNK;
    if (start >= seq) return;
    int end   = min(seq, start + CHUNK);
    int slot  = slot_map[b];

    int tid  = threadIdx.x;
    int lane = tid & 31;
    int warp = tid >> 5;     // 0..3
    int sg   = lane >> 3;    // subgroup 0..3 -> token offset
    int li   = lane & 7;     // dim sub-chunk within subgroup

    // ---- q (scaled) to smem ----
    {
        float4 q4 = *reinterpret_cast<const float4*>(
            &g_qkv[b * QKV_OUT + kvh * GROUP * HEAD_DIM + tid * 4]);
        q4.x *= QSCALE; q4.y *= QSCALE; q4.z *= QSCALE; q4.w *= QSCALE;
        *reinterpret_cast<float4*>(&sm_q[tid * 4]) = q4;
    }
    __syncthreads();

    unsigned qaddr = (unsigned)__cvta_generic_to_shared(sm_q) + (li * 4) * 4;

    const size_t VPLANE = (size_t)BSZ * MAX_SEQ * NUM_KV * HEAD_DIM;
    const float* knew = &g_qkv[b * QKV_OUT + NUM_HEADS * HEAD_DIM            + kvh * HEAD_DIM];
    const float* vnew = &g_qkv[b * QKV_OUT + (NUM_HEADS + NUM_KV) * HEAD_DIM + kvh * HEAD_DIM];

    float m_run[4], m_base[4], l[4];
    unsigned long long o[4][2];
    #pragma unroll
    for (int g = 0; g < 4; g++) {
        m_run[g] = -1e30f; m_base[g] = -1e30f; l[g] = 0.f;
        o[g][0] = 0ull; o[g][1] = 0ull;
    }

    for (int s0 = start + warp * 4; s0 < end; s0 += 16) {
        // ---- K load: subgroup sg owns token s0+sg, lane owns dims i*32+li*4 ----
        int stok = s0 + sg;
        int sk   = min(stok, end - 1);
        const float* kp = (sk == slot) ? knew
            : &kvc[(((size_t)b * MAX_SEQ + sk) * NUM_KV + kvh) * HEAD_DIM];
        float4 k4[4];
        #pragma unroll
        for (int i = 0; i < 4; i++)
            k4[i] = *reinterpret_cast<const float4*>(&kp[i * 32 + li * 4]);

        // ---- V load: lane owns dims lane*4 of all 4 tokens ----
        float4 v4[4];
        #pragma unroll
        for (int t = 0; t < 4; t++) {
            int sv = min(s0 + t, end - 1);
            const float* vp = (sv == slot) ? vnew
                : &kvc[VPLANE + (((size_t)b * MAX_SEQ + sv) * NUM_KV + kvh) * HEAD_DIM];
            v4[t] = *reinterpret_cast<const float4*>(&vp[lane * 4]);
        }

        // ---- scores: 16-dim partial dot per lane, per group ----
        float scg[4];
        #pragma unroll
        for (int g = 0; g < 4; g++) {
            float4 q0, q1, q2, q3;
            unsigned qa = qaddr + g * 512;
            lds128(q0, qa);       lds128(q1, qa + 128);
            lds128(q2, qa + 256); lds128(q3, qa + 384);
            unsigned long long acc = 0ull;
            ulonglong2 qp, kk;
            qp = *reinterpret_cast<const ulonglong2*>(&q0);
            kk = *reinterpret_cast<const ulonglong2*>(&k4[0]);
            fma2(acc, qp.x, kk.x); fma2(acc, qp.y, kk.y);
            qp = *reinterpret_cast<const ulonglong2*>(&q1);
            kk = *reinterpret_cast<const ulonglong2*>(&k4[1]);
            fma2(acc, qp.x, kk.x); fma2(acc, qp.y, kk.y);
            qp = *reinterpret_cast<const ulonglong2*>(&q2);
            kk = *reinterpret_cast<const ulonglong2*>(&k4[2]);
            fma2(acc, qp.x, kk.x); fma2(acc, qp.y, kk.y);
            qp = *reinterpret_cast<const ulonglong2*>(&q3);
            kk = *reinterpret_cast<const ulonglong2*>(&k4[3]);
            fma2(acc, qp.x, kk.x); fma2(acc, qp.y, kk.y);
            float lo, hi; unpack2(acc, lo, hi);
            scg[g] = lo + hi;
        }
        // butterfly within 8-lane subgroup
        #pragma unroll
        for (int g = 0; g < 4; g++) {
            scg[g] += __shfl_xor_sync(0xffffffffu, scg[g], 4);
            scg[g] += __shfl_xor_sync(0xffffffffu, scg[g], 2);
            scg[g] += __shfl_xor_sync(0xffffffffu, scg[g], 1);
        }
        // mask invalid own-token
        bool valid = (stok < end);
        #pragma unroll
        for (int g = 0; g < 4; g++)
            scg[g] = valid ? scg[g] : -CUDART_INF_F;

        // gather all 4 tokens' scores (warp-uniform state from here)
        float sct[4][4];
        #pragma unroll
        for (int g = 0; g < 4; g++) {
            sct[0][g] = __shfl_sync(0xffffffffu, scg[g], 0);
            sct[1][g] = __shfl_sync(0xffffffffu, scg[g], 8);
            sct[2][g] = __shfl_sync(0xffffffffu, scg[g], 16);
            sct[3][g] = __shfl_sync(0xffffffffu, scg[g], 24);
        }

        // ---- softmax: deferred-rescale base-max (warp-uniform branch) ----
        #pragma unroll
        for (int g = 0; g < 4; g++)
            m_run[g] = fmaxf(fmaxf(fmaxf(sct[0][g], sct[1][g]),
                                   fmaxf(sct[2][g], sct[3][g])), m_run[g]);
        float need = fmaxf(fmaxf(m_run[0] - m_base[0], m_run[1] - m_base[1]),
                           fmaxf(m_run[2] - m_base[2], m_run[3] - m_base[3]));
        if (need > 30.f) {
            #pragma unroll
            for (int g = 0; g < 4; g++) {
                float corr = exp2f(m_base[g] - m_run[g]);
                l[g] *= corr;
                unsigned long long cd = dup2(corr);
                mul2(o[g][0], cd); mul2(o[g][1], cd);
                m_base[g] = m_run[g];
            }
        }
        #pragma unroll
        for (int g = 0; g < 4; g++) {
            float p0 = exp2f(sct[0][g] - m_base[g]);
            float p1 = exp2f(sct[1][g] - m_base[g]);
            float p2 = exp2f(sct[2][g] - m_base[g]);
            float p3 = exp2f(sct[3][g] - m_base[g]);
            l[g] += (p0 + p1) + (p2 + p3);
            unsigned long long pd;
            ulonglong2 vp;
            vp = *reinterpret_cast<const ulonglong2*>(&v4[0]);
            pd = dup2(p0); fma2(o[g][0], vp.x, pd); fma2(o[g][1], vp.y, pd);
            vp = *reinterpret_cast<const ulonglong2*>(&v4[1]);
            pd = dup2(p1); fma2(o[g][0], vp.x, pd); fma2(o[g][1], vp.y, pd);
            vp = *reinterpret_cast<const ulonglong2*>(&v4[2]);
            pd = dup2(p2); fma2(o[g][0], vp.x, pd); fma2(o[g][1], vp.y, pd);
            vp = *reinterpret_cast<const ulonglong2*>(&v4[3]);
            pd = dup2(p3); fma2(o[g][0], vp.x, pd); fma2(o[g][1], vp.y, pd);
        }
    }

    // ---- cross-warp merge ----
    #pragma unroll
    for (int g = 0; g < 4; g++) {
        float l0, h0, l1, h1;
        unpack2(o[g][0], l0, h0);
        unpack2(o[g][1], l1, h1);
        *reinterpret_cast<float4*>(&sm_o[warp][g][lane * 4]) =
            make_float4(l0, h0, l1, h1);
    }
    if (lane == 0) {
        #pragma unroll
        for (int g = 0; g < 4; g++) { sm_m[warp][g] = m_base[g]; sm_l[warp][g] = l[g]; }
    }
    __syncthreads();

    if (warp == 0 && lane < 16) {
        int w = lane & 3, g = lane >> 2;
        float mm = sm_m[w][g], ll = sm_l[w][g];
        float M = mm;
        M = fmaxf(M, __shfl_xor_sync(0x0000ffffu, M, 1));
        M = fmaxf(M, __shfl_xor_sync(0x0000ffffu, M, 2));
        float e = exp2f(mm - M);
        float le = ll * e;
        le += __shfl_xor_sync(0x0000ffffu, le, 1);
        le += __shfl_xor_sync(0x0000ffffu, le, 2);
        sm_e[w][g] = e;
        if (w == 0) {
            size_t pidx = (((size_t)b * NUM_KV + kvh) * GROUP + g) * NCHUNK + c;
            g_pml[pidx * 2]     = M;
            g_pml[pidx * 2 + 1] = le;
        }
    }
    __syncthreads();

    {
        int d = tid;   // 0..127
        #pragma unroll
        for (int g = 0; g < 4; g++) {
            float sum = sm_o[0][g][d] * sm_e[0][g]
                      + sm_o[1][g][d] * sm_e[1][g]
                      + sm_o[2][g][d] * sm_e[2][g]
                      + sm_o[3][g][d] * sm_e[3][g];
            size_t pidx = (((size_t)b * NUM_KV + kvh) * GROUP + g) * NCHUNK + c;
            g_po[pidx * HEAD_DIM + d] = sum;
        }
    }
}

// ---------------------------------------------------------------
// Chunk merge (unchanged)
// ---------------------------------------------------------------
__global__ void __launch_bounds__(128)
attn_reduce_kernel(const int* __restrict__ seq_lens)
{
    int h = blockIdx.x;
    int b = blockIdx.y;
    int d = threadIdx.x;
    int lane = d & 31, warp = d >> 5;
    int seq = seq_lens[b];
    int nch = (seq + CHUNK - 1) / CHUNK;
    int kvh = h >> 2, g = h & 3;

    size_t base = (((size_t)b * NUM_KV + kvh) * GROUP + g) * NCHUNK;

    __shared__ float es[NCHUNK];
    __shared__ float Ls;

    if (warp == 0) {
        float mm = -CUDART_INF_F, ll = 0.f;
        if (lane < nch) {
            float2 ml = *reinterpret_cast<const float2*>(&g_pml[(base + lane) * 2]);
            mm = ml.x; ll = ml.y;
        }
        float M = mm;
        #pragma unroll
        for (int off = 16; off >= 1; off >>= 1)
            M = fmaxf(M, __shfl_xor_sync(0xffffffffu, M, off));
        float e = (lane < nch) ? exp2f(mm - M) : 0.f;
        float le = ll * e;
        #pragma unroll
        for (int off = 16; off >= 1; off >>= 1)
            le += __shfl_xor_sync(0xffffffffu, le, off);
        es[lane] = e;
        if (lane == 0) Ls = le;
    }
    __syncthreads();

    float O0 = 0.f, O1 = 0.f, O2 = 0.f, O3 = 0.f;
    int cc = 0;
    for (; cc + 4 <= nch; cc += 4) {
        O0 += g_po[(base + cc + 0) * HEAD_DIM + d] * es[cc + 0];
        O1 += g_po[(base + cc + 1) * HEAD_DIM + d] * es[cc + 1];
        O2 += g_po[(base + cc + 2) * HEAD_DIM + d] * es[cc + 2];
        O3 += g_po[(base + cc + 3) * HEAD_DIM + d] * es[cc + 3];
    }
    for (; cc < nch; cc++)
        O0 += g_po[(base + cc) * HEAD_DIM + d] * es[cc];

    g_attn[(size_t)b * HIDDEN + h * HEAD_DIM + d] = ((O0 + O1) + (O2 + O3)) / Ls;
}

// ---------------------------------------------------------------
extern "C" void kernel_launch(void* const* d_in, const int* in_sizes, int n_in,
                              void* d_out, int out_size)
{
    const float* hidden = (const float*)d_in[0];
    const float* kvc    = (const float*)d_in[2];
    const int*   slot   = (const int*)  d_in[3];
    const int*   seql   = (const int*)  d_in[4];
    const float* Wqkv   = (const float*)d_in[5];
    const float* bqkv   = (const float*)d_in[6];
    const float* Wo     = (const float*)d_in[7];
    float*       out    = (float*)d_out;

    void *pq = nullptr, *pa = nullptr, *pp = nullptr;
    cudaGetSymbolAddress(&pq, g_qkv);
    cudaGetSymbolAddress(&pa, g_attn);
    cudaGetSymbolAddress(&pp, g_part);
    float* qkv  = (float*)pq;
    float* attn = (float*)pa;
    float* part = (float*)pp;

    // 1) QKV projection: partials + reduce (bias folded into reduce)
    gemm8x8_kernel<<<dim3(QKV_OUT / GBM, QKV_SPLIT), 256>>>(Wqkv, hidden, part, QKV_OUT, HIDDEN, QKV_SPLIT);
    reduce_part_kernel<<<(BSZ * QKV_OUT / 4 + 255) / 256, 256>>>(
        (const float4*)part, (const float4*)bqkv, (float4*)qkv, QKV_OUT / 4, QKV_SPLIT);

    // 2) flash-decode partials (subgroup-of-8 online kernel)
    attn_partial_kernel<<<dim3(NCHUNK, NUM_KV, BSZ), 128>>>(kvc, seql, slot);

    // 3) merge partials
    attn_reduce_kernel<<<dim3(NUM_HEADS, BSZ), 128>>>(seql);

    // 4) output projection: partials + reduce (writes d_out directly)
    gemm8x8_kernel<<<dim3(HIDDEN / GBM, WO_SPLIT), 256>>>(Wo, attn, part, HIDDEN, HIDDEN, WO_SPLIT);
    reduce_part_kernel<<<(BSZ * HIDDEN / 4 + 255) / 256, 256>>>(
        (const float4*)part, nullptr, (float4*)out, HIDDEN / 4, WO_SPLIT);
}